// round 2
// baseline (speedup 1.0000x reference)
#include <cuda_runtime.h>

#define T_STEPS 128
#define BATCH   256
#define D1      2048
#define D2      2048

#define BM 64
#define BN 64
#define BK 32

// Persistent recurrence state (re-zeroed every kernel_launch call for determinism)
__device__ float g_syn[BATCH * D2];
__device__ float g_mem[BATCH * D2];

__global__ void init_state_kernel() {
    int i = blockIdx.x * blockDim.x + threadIdx.x;
    if (i < BATCH * D2) {
        g_syn[i] = 0.0f;
        g_mem[i] = 0.0f;
    }
}

// One timestep: cur = x_t @ W^T  (both operands K-major / contiguous along D1),
// fused with the synaptic/membrane recurrence + spike write.
__global__ __launch_bounds__(256, 2)
void step_kernel(const float* __restrict__ x,
                 const float* __restrict__ W,
                 float* __restrict__ out,
                 int t) {
    __shared__ float Xs[BK][BM];   // transposed: [k][row]
    __shared__ float Ws[BK][BN];   // transposed: [k][col]

    const int tid = threadIdx.x;       // 0..255
    const int tx  = tid & 15;          // 0..15 -> d2 micro
    const int ty  = tid >> 4;          // 0..15 -> batch micro
    const int bN  = blockIdx.x;        // d2 tile
    const int bM  = blockIdx.y;        // batch tile

    const float* xt = x + (size_t)t * BATCH * D1 + (size_t)bM * BM * D1;
    const float* Wp = W + (size_t)bN * BN * D1;

    float acc[4][4];
#pragma unroll
    for (int i = 0; i < 4; i++)
#pragma unroll
        for (int j = 0; j < 4; j++) acc[i][j] = 0.0f;

    const int r  = tid & 63;   // row within tile (0..63)
    const int v0 = tid >> 6;   // 0..3 -> which float4 chunk

    for (int k0 = 0; k0 < D1; k0 += BK) {
#pragma unroll
        for (int h = 0; h < 2; h++) {
            const int v = v0 + h * 4;   // 0..7, covers 32 floats per row
            float4 xa = *(const float4*)(xt + (size_t)r * D1 + k0 + v * 4);
            float4 wa = *(const float4*)(Wp + (size_t)r * D1 + k0 + v * 4);
            Xs[v * 4 + 0][r] = xa.x;
            Xs[v * 4 + 1][r] = xa.y;
            Xs[v * 4 + 2][r] = xa.z;
            Xs[v * 4 + 3][r] = xa.w;
            Ws[v * 4 + 0][r] = wa.x;
            Ws[v * 4 + 1][r] = wa.y;
            Ws[v * 4 + 2][r] = wa.z;
            Ws[v * 4 + 3][r] = wa.w;
        }
        __syncthreads();

#pragma unroll
        for (int kk = 0; kk < BK; kk++) {
            float4 a = *(const float4*)&Xs[kk][ty * 4];
            float4 b = *(const float4*)&Ws[kk][tx * 4];
            float av[4] = {a.x, a.y, a.z, a.w};
            float bv[4] = {b.x, b.y, b.z, b.w};
#pragma unroll
            for (int i = 0; i < 4; i++)
#pragma unroll
                for (int j = 0; j < 4; j++)
                    acc[i][j] = fmaf(av[i], bv[j], acc[i][j]);
        }
        __syncthreads();
    }

    // Fused recurrence epilogue
    const float ALPHA = (float)(1.0 - 0.001 / 0.005);  // 0.8
    const float BETA  = (float)(1.0 - 0.001 / 0.01);   // 0.9

    float* out_t = out + (size_t)t * BATCH * D2;
#pragma unroll
    for (int i = 0; i < 4; i++) {
        const int b_idx = bM * BM + ty * 4 + i;
#pragma unroll
        for (int j = 0; j < 4; j++) {
            const int jj = bN * BN + tx * 4 + j;
            const size_t sidx = (size_t)b_idx * D2 + jj;

            float cur     = acc[i][j];
            float syn     = ALPHA * g_syn[sidx] + cur;
            float mem_old = g_mem[sidx];
            float mem_new = BETA * mem_old + syn;
            if (mem_old > 1.0f) mem_new = 0.0f;   // zero reset (prev mem, detached)

            g_syn[sidx] = syn;
            g_mem[sidx] = mem_new;
            out_t[sidx] = (mem_new > 1.0f) ? 1.0f : 0.0f;
        }
    }
}

extern "C" void kernel_launch(void* const* d_in, const int* in_sizes, int n_in,
                              void* d_out, int out_size) {
    const float* x = (const float*)d_in[0];   // [T, B, D1]
    const float* W = (const float*)d_in[1];   // [D2, D1]
    float* out = (float*)d_out;               // [T, B, D2]

    init_state_kernel<<<(BATCH * D2 + 511) / 512, 512>>>();

    dim3 grid(D2 / BN, BATCH / BM);   // (32, 4) = 128 CTAs
    for (int t = 0; t < T_STEPS; t++) {
        step_kernel<<<grid, 256>>>(x, W, out, t);
    }
}

// round 7
// speedup vs baseline: 11.7138x; 11.7138x over previous
#include <cuda_runtime.h>
#include <cstdint>

#define T_STEPS 128
#define BATCH   256
#define D1      2048
#define D2      2048
#define M_TOTAL (T_STEPS * BATCH)      // 32768 GEMM rows

#define BM 128          // CTA tile M
#define BN 64           // CTA tile N
#define BK 128          // K chunk in int8 elements (= one 128B smem row)
#define NSTAGE 3
#define NCHUNK (D1 / BK)               // 16
#define NPLANE 4

#define A_STAGE (BM * 128)                         // 16384
#define B_PLANE (BN * 128)                         // 8192 per digit plane
#define STAGE_BYTES (A_STAGE + NPLANE * B_PLANE)   // 49152
#define SMEM_BYTES  (NSTAGE * STAGE_BYTES)         // 147456

// W quantization: I = llrint(W * 2^33) computed in DOUBLE, 4 signed base-256 digits.
// Quantization error per weight <= 2^-34 -> negligible vs fp32 rounding of reference.
#define INV_WSCALE 1.16415321826934814453125e-10f   // 2^-33 (exact in fp32)

__device__ int8_t g_x8[(size_t)M_TOTAL * D1];            // binary x as int8 (exact)
__device__ int8_t g_w8[(size_t)NPLANE * D2 * D1];        // digit planes c0..c3
__device__ float  g_cur[(size_t)M_TOTAL * D2];           // fp32 currents

static __device__ __forceinline__ uint32_t smem_u32(const void* p) {
    uint32_t a;
    asm("{ .reg .u64 t; cvta.to.shared.u64 t, %1; cvt.u32.u64 %0, t; }" : "=r"(a) : "l"(p));
    return a;
}
static __device__ __forceinline__ void cp16(uint32_t s, const void* g) {
    asm volatile("cp.async.cg.shared.global [%0], [%1], 16;" :: "r"(s), "l"(g) : "memory");
}
#define CP_COMMIT()  asm volatile("cp.async.commit_group;" ::: "memory")
#define CP_WAIT1()   asm volatile("cp.async.wait_group 1;" ::: "memory")

static __device__ __forceinline__ void ldsm4(uint32_t* r, uint32_t addr) {
    asm volatile("ldmatrix.sync.aligned.m8n8.x4.shared.b16 {%0,%1,%2,%3}, [%4];"
                 : "=r"(r[0]), "=r"(r[1]), "=r"(r[2]), "=r"(r[3]) : "r"(addr));
}
// s8 mma: D(s32) = A(s8, m16k32 row) * B(s8, k32n8 col) + D — EXACT integer arithmetic
static __device__ __forceinline__ void mma_s8(int* c, const uint32_t* a,
                                              uint32_t b0, uint32_t b1) {
    asm volatile(
        "mma.sync.aligned.m16n8k32.row.col.s32.s8.s8.s32 "
        "{%0,%1,%2,%3}, {%4,%5,%6,%7}, {%8,%9}, {%0,%1,%2,%3};"
        : "+r"(c[0]), "+r"(c[1]), "+r"(c[2]), "+r"(c[3])
        : "r"(a[0]), "r"(a[1]), "r"(a[2]), "r"(a[3]), "r"(b0), "r"(b1));
}

// swizzled byte offset of (row, 16B-chunk kb) within a 128B-row tile
static __device__ __forceinline__ uint32_t swz(int row, int kb) {
    return (uint32_t)(row * 128 + ((kb ^ (row & 7)) << 4));
}

// ---------------- prep kernels ----------------

__global__ void prep_x_kernel(const float* __restrict__ x) {
    const size_t n = (size_t)M_TOTAL * D1;
    const size_t stride = (size_t)gridDim.x * blockDim.x * 4;
    for (size_t i = ((size_t)blockIdx.x * blockDim.x + threadIdx.x) * 4; i < n; i += stride) {
        float4 v = *(const float4*)(x + i);
        char4 c;
        c.x = (char)v.x; c.y = (char)v.y; c.z = (char)v.z; c.w = (char)v.w;  // x in {0.0, 1.0}
        *(char4*)(g_x8 + i) = c;
    }
}

__global__ void prep_w_kernel(const float* __restrict__ W) {
    const size_t n = (size_t)D2 * D1;
    const size_t stride = (size_t)gridDim.x * blockDim.x;
    for (size_t i = (size_t)blockIdx.x * blockDim.x + threadIdx.x; i < n; i += stride) {
        // exact in double: W has 24-bit mantissa, * 2^33 is exact, llrint once
        double wd = (double)W[i] * 8589934592.0;          // W * 2^33
        long long I = llrint(wd);
        I = min(max(I, -2130000000LL), 2130000000LL);     // inert safety clamp (|W|<0.25)
        int c3 = (int)((I + 128) & 255) - 128;  I = (I - c3) >> 8;
        int c2 = (int)((I + 128) & 255) - 128;  I = (I - c2) >> 8;
        int c1 = (int)((I + 128) & 255) - 128;  I = (I - c1) >> 8;
        int c0 = (int)I;                                   // |c0| <= 127
        g_w8[i]         = (int8_t)c0;
        g_w8[n + i]     = (int8_t)c1;
        g_w8[2 * n + i] = (int8_t)c2;
        g_w8[3 * n + i] = (int8_t)c3;
    }
}

// ---------------- GEMM: g_cur = x @ W^T, exact fixed-point via int8 tensor cores ----
// grid (D2/BN, M_TOTAL/BM) = (32, 256), 256 threads (8 warps: 4x2 grid, 32x32 warp tile)

__global__ void __launch_bounds__(256, 1)
gemm_kernel() {
    extern __shared__ char smem[];
    const uint32_t sb = smem_u32(smem);
    const int tid   = threadIdx.x;
    const int wid   = tid >> 5;
    const int lane  = tid & 31;
    const int warpM = wid & 3;           // 0..3 -> 32-row slab
    const int warpN = wid >> 2;          // 0..1 -> 32-col slab
    const int bN    = blockIdx.x;
    const int bM    = blockIdx.y;

    const int8_t* gA = g_x8 + (size_t)bM * BM * D1;
    const int8_t* gB = g_w8 + (size_t)bN * BN * D1;   // + plane * D2*D1

    // ldmatrix per-lane fragment rows and 16B-chunk parities (validated layout)
    const int a_r  = (lane & 7) + ((lane >> 3) & 1) * 8;
    const int a_ks = lane >> 4;
    const int b_r  = (lane & 7) + ((lane >> 4) & 1) * 8;
    const int b_ks = (lane >> 3) & 1;

    int acc[NPLANE][2][4][4];
#pragma unroll
    for (int p = 0; p < NPLANE; p++)
#pragma unroll
        for (int mi = 0; mi < 2; mi++)
#pragma unroll
            for (int ni = 0; ni < 4; ni++)
#pragma unroll
                for (int e = 0; e < 4; e++) acc[p][mi][ni][e] = 0;

    // stage loader: A 1024 + B 4*512 16B chunks, 12 per thread
    auto load_stage = [&](int kc, int slot) {
        const uint32_t st = sb + slot * STAGE_BYTES;
#pragma unroll
        for (int i = 0; i < 4; i++) {
            const int u = tid + 256 * i;
            const int row = u >> 3, kb = u & 7;
            cp16(st + swz(row, kb), gA + (size_t)row * D1 + kc * BK + kb * 16);
        }
#pragma unroll
        for (int i = 0; i < 8; i++) {
            const int u  = tid + 256 * i;
            const int sp = u >> 9;                 // plane 0..3 (512 chunks each)
            const int v  = u & 511;
            const int row = v >> 3, kb = v & 7;    // row 0..63
            cp16(st + A_STAGE + sp * B_PLANE + swz(row, kb),
                 gB + (size_t)sp * D2 * D1 + (size_t)row * D1 + kc * BK + kb * 16);
        }
    };

    load_stage(0, 0); CP_COMMIT();
    load_stage(1, 1); CP_COMMIT();

    for (int kc = 0; kc < NCHUNK; kc++) {
        CP_WAIT1();
        __syncthreads();
        if (kc + 2 < NCHUNK) load_stage(kc + 2, (kc + 2) % NSTAGE);
        CP_COMMIT();

        const uint32_t stA = sb + (kc % NSTAGE) * STAGE_BYTES;
        const uint32_t stB = stA + A_STAGE;
#pragma unroll
        for (int ks = 0; ks < 4; ks++) {             // k32 steps within 128-elem chunk
            uint32_t afrag[2][4];
#pragma unroll
            for (int mi = 0; mi < 2; mi++) {
                const int row = warpM * 32 + mi * 16 + a_r;
                const int kb  = ks * 2 + a_ks;
                ldsm4(afrag[mi], stA + swz(row, kb));
            }
#pragma unroll
            for (int p = 0; p < NPLANE; p++) {
#pragma unroll
                for (int ng = 0; ng < 2; ng++) {      // n16 groups within 32-col slab
                    uint32_t bf[4];
                    const int row = warpN * 32 + ng * 16 + b_r;
                    const int kb  = ks * 2 + b_ks;
                    ldsm4(bf, stB + p * B_PLANE + swz(row, kb));
                    mma_s8(acc[p][0][ng * 2 + 0], afrag[0], bf[0], bf[1]);
                    mma_s8(acc[p][0][ng * 2 + 1], afrag[0], bf[2], bf[3]);
                    mma_s8(acc[p][1][ng * 2 + 0], afrag[1], bf[0], bf[1]);
                    mma_s8(acc[p][1][ng * 2 + 1], afrag[1], bf[2], bf[3]);
                }
            }
        }
    }

    // epilogue: exact int64 digit recombination -> one RN convert -> fp32 currents
    const int g  = lane >> 2;
    const int tq = lane & 3;
    float* outBase = g_cur + (size_t)(bM * BM + warpM * 32) * D2 + bN * BN + warpN * 32;
#pragma unroll
    for (int mi = 0; mi < 2; mi++)
#pragma unroll
        for (int ni = 0; ni < 4; ni++) {
            float r[4];
#pragma unroll
            for (int e = 0; e < 4; e++) {
                long long V = ((long long)acc[0][mi][ni][e] << 24)
                            + ((long long)acc[1][mi][ni][e] << 16)
                            + ((long long)acc[2][mi][ni][e] << 8)
                            +  (long long)acc[3][mi][ni][e];
                r[e] = (float)V * INV_WSCALE;
            }
            float* ptr = outBase + (size_t)(mi * 16 + g) * D2 + ni * 8 + tq * 2;
            *(float2*)ptr                    = make_float2(r[0], r[1]);
            *(float2*)(ptr + 8 * (size_t)D2) = make_float2(r[2], r[3]);
        }
}

// ---------------- scan: recurrence over t, elementwise in (b, d2) ----------------

__global__ void __launch_bounds__(256, 8)
scan_kernel(float* __restrict__ out) {
    const int gid = blockIdx.x * blockDim.x + threadIdx.x;   // 0..131071
    const size_t base = (size_t)gid * 4;

    const float ALPHA = (float)(1.0 - 0.001 / 0.005);  // 0.8
    const float BETA  = (float)(1.0 - 0.001 / 0.01);   // 0.9

    float syn[4] = {0, 0, 0, 0}, mem[4] = {0, 0, 0, 0};
    for (int t = 0; t < T_STEPS; t++) {
        const size_t idx = (size_t)t * BATCH * D2 + base;
        float4 cur = *(const float4*)(g_cur + idx);
        const float cv[4] = {cur.x, cur.y, cur.z, cur.w};
        float4 spk;
        float* sv = (float*)&spk;
#pragma unroll
        for (int e = 0; e < 4; e++) {
            syn[e] = ALPHA * syn[e] + cv[e];
            float mn = BETA * mem[e] + syn[e];
            if (mem[e] > 1.0f) mn = 0.0f;            // zero reset (uses previous mem)
            sv[e] = (mn > 1.0f) ? 1.0f : 0.0f;
            mem[e] = mn;
        }
        *(float4*)(out + idx) = spk;
    }
}

extern "C" void kernel_launch(void* const* d_in, const int* in_sizes, int n_in,
                              void* d_out, int out_size) {
    const float* x = (const float*)d_in[0];   // [T, B, D1]
    const float* W = (const float*)d_in[1];   // [D2, D1]
    float* out = (float*)d_out;               // [T, B, D2]

    cudaFuncSetAttribute(gemm_kernel, cudaFuncAttributeMaxDynamicSharedMemorySize, SMEM_BYTES);

    prep_x_kernel<<<4096, 256>>>(x);
    prep_w_kernel<<<4096, 256>>>(W);

    dim3 grid(D2 / BN, M_TOTAL / BM);         // (32, 256)
    gemm_kernel<<<grid, 256, SMEM_BYTES>>>();

    scan_kernel<<<(BATCH * D2 / 4) / 256, 256>>>(out);
}